// round 3
// baseline (speedup 1.0000x reference)
#include <cuda_runtime.h>

// Problem constants (fixed by the reference).
#define BB   64
#define TT   512
#define VV   96
#define HH   1024
#define NCTA 128   // persistent grid for the recurrence kernel (8 k-chunks x 16 col-tiles)

// ---------------------------------------------------------------------------
// Scratch (device globals: allocation-free per harness rules)
// ---------------------------------------------------------------------------
__device__ float g_xproj[(size_t)BB * TT * HH];     // 128 MB: x @ Wxh + bh, layout [b][t][h]
__device__ float g_hs   [(size_t)BB * TT * HH];     // 128 MB: hidden states, layout [b][t][h]
__device__ float g_partial[8 * BB * HH];            // 2 MB: split-K partials [kc][b][j]
__device__ unsigned g_cnt = 0;
__device__ volatile unsigned g_gen = 0;

// ---------------------------------------------------------------------------
// Global software barrier (sense via monotonically increasing generation).
// Grid must be fully co-resident: 128 CTAs of 256 thr / ~34KB smem on 148 SMs -> 1 CTA/SM.
// All cross-CTA data is read with __ldcg (L2) so the fence protocol is sound:
// stores drain to L2 before the arrive (threadfence), readers pull from L2.
// ---------------------------------------------------------------------------
__device__ __forceinline__ void gbar()
{
    __syncthreads();
    if (threadIdx.x == 0) {
        __threadfence();                      // release: prior global stores visible
        unsigned g = g_gen;                   // safe: gen can't bump until *we* arrive
        if (atomicAdd(&g_cnt, 1u) == NCTA - 1) {
            g_cnt = 0;                        // reset for next barrier
            __threadfence();                  // order reset before release
            g_gen = g + 1;                    // release all spinners
        } else {
            while (g_gen == g) { __nanosleep(64); }
        }
        __threadfence();                      // acquire
    }
    __syncthreads();
}

// ---------------------------------------------------------------------------
// Kernel 1: xproj[r][j] = sum_v x[r][v] * Wxh[v][j] + bh[j]   (r = b*T + t)
// 64x64 output tile per CTA, K=96 in chunks of 32, 4x4 thread tile.
// ---------------------------------------------------------------------------
__global__ void __launch_bounds__(256) xproj_kernel(const float* __restrict__ x,
                                                    const float* __restrict__ Wxh,
                                                    const float* __restrict__ bh)
{
    __shared__ float sa[64][36];   // [row][k], row stride 144B (16B aligned)
    __shared__ float sw[32][64];   // [k][j]

    const int tid = threadIdx.x;
    const int tx  = tid & 15;
    const int ty  = tid >> 4;
    const size_t row0 = (size_t)blockIdx.y * 64;
    const int jt  = blockIdx.x;            // 0..15 -> columns jt*64..

    float acc[4][4] = {};

    #pragma unroll 1
    for (int K0 = 0; K0 < 96; K0 += 32) {
        #pragma unroll
        for (int i = 0; i < 2; ++i) {      // 512 float4 of A
            int idx = tid + i * 256;
            int r = idx >> 3, k4 = (idx & 7) * 4;
            float4 v = *(const float4*)(x + (row0 + r) * 96 + K0 + k4);
            *(float4*)&sa[r][k4] = v;
        }
        #pragma unroll
        for (int i = 0; i < 2; ++i) {      // 512 float4 of W
            int idx = tid + i * 256;
            int kk = idx >> 4, j4 = (idx & 15) * 4;
            float4 v = *(const float4*)(Wxh + (size_t)(K0 + kk) * HH + jt * 64 + j4);
            *(float4*)&sw[kk][j4] = v;
        }
        __syncthreads();
        #pragma unroll 4
        for (int k = 0; k < 32; k += 4) {
            float ha[4][4], wa[4][4];
            #pragma unroll
            for (int i = 0; i < 4; ++i) {
                float4 v = *(const float4*)&sa[ty * 4 + i][k];
                ha[i][0] = v.x; ha[i][1] = v.y; ha[i][2] = v.z; ha[i][3] = v.w;
            }
            #pragma unroll
            for (int kk = 0; kk < 4; ++kk) {
                float4 v = *(const float4*)&sw[k + kk][tx * 4];
                wa[kk][0] = v.x; wa[kk][1] = v.y; wa[kk][2] = v.z; wa[kk][3] = v.w;
            }
            #pragma unroll
            for (int kk = 0; kk < 4; ++kk)
                #pragma unroll
                for (int i = 0; i < 4; ++i)
                    #pragma unroll
                    for (int j = 0; j < 4; ++j)
                        acc[i][j] += ha[i][kk] * wa[kk][j];
        }
        __syncthreads();
    }

    float4 bv = *(const float4*)(bh + jt * 64 + tx * 4);
    #pragma unroll
    for (int i = 0; i < 4; ++i) {
        float4 v = make_float4(acc[i][0] + bv.x, acc[i][1] + bv.y,
                               acc[i][2] + bv.z, acc[i][3] + bv.w);
        *(float4*)&g_xproj[(row0 + ty * 4 + i) * HH + jt * 64 + tx * 4] = v;
    }
}

// ---------------------------------------------------------------------------
// Kernel 2: persistent recurrence. 128 CTAs, 2 phases per timestep.
//   Phase 1: CTA (kc,jt): partial[kc][b][jt*64+j] = sum_{k in kc-chunk} h[b][k]*Whh[k][j]
//   Phase 2: h_t[b][j] = tanh(xproj[b][t][j] + sum_kc partial), written to g_hs[b][t][j]
// ---------------------------------------------------------------------------
__global__ void __launch_bounds__(256) rnn_kernel(const float* __restrict__ h0,
                                                  const float* __restrict__ Whh)
{
    __shared__ float sh[64][68];   // [b][k], row stride 272B (16B aligned)
    __shared__ float sw[64][64];   // [k][j]

    const int tid = threadIdx.x;
    const int bx  = blockIdx.x;
    const int kc  = bx >> 4;       // 0..7  (K chunk of 128)
    const int jt  = bx & 15;       // 0..15 (64-column tile)
    const int tx  = tid & 15;
    const int ty  = tid >> 4;

    for (int t = 0; t < TT; ++t) {
        const float* hb;
        size_t bstr;
        if (t == 0) { hb = h0;                          bstr = HH; }
        else        { hb = g_hs + (size_t)(t - 1) * HH; bstr = (size_t)TT * HH; }

        float acc[4][4] = {};

        #pragma unroll 1
        for (int ks = 0; ks < 2; ++ks) {
            const int K0 = kc * 128 + ks * 64;
            // h tile: 64 rows (all batch) x 64 k. Cross-CTA data -> L2 loads.
            #pragma unroll
            for (int i = 0; i < 4; ++i) {
                int idx = tid + i * 256;
                int bb = idx >> 4, k4 = (idx & 15) * 4;
                float4 v = __ldcg((const float4*)(hb + (size_t)bb * bstr + K0 + k4));
                *(float4*)&sh[bb][k4] = v;
            }
            // Whh tile: 64 k x 64 j (read-only, L1 ok)
            #pragma unroll
            for (int i = 0; i < 4; ++i) {
                int idx = tid + i * 256;
                int kk = idx >> 4, j4 = (idx & 15) * 4;
                float4 v = *(const float4*)(Whh + (size_t)(K0 + kk) * HH + jt * 64 + j4);
                *(float4*)&sw[kk][j4] = v;
            }
            __syncthreads();
            #pragma unroll 4
            for (int k = 0; k < 64; k += 4) {
                float ha[4][4], wa[4][4];
                #pragma unroll
                for (int i = 0; i < 4; ++i) {
                    float4 v = *(const float4*)&sh[ty * 4 + i][k];
                    ha[i][0] = v.x; ha[i][1] = v.y; ha[i][2] = v.z; ha[i][3] = v.w;
                }
                #pragma unroll
                for (int kk = 0; kk < 4; ++kk) {
                    float4 v = *(const float4*)&sw[k + kk][tx * 4];
                    wa[kk][0] = v.x; wa[kk][1] = v.y; wa[kk][2] = v.z; wa[kk][3] = v.w;
                }
                #pragma unroll
                for (int kk = 0; kk < 4; ++kk)
                    #pragma unroll
                    for (int i = 0; i < 4; ++i)
                        #pragma unroll
                        for (int j = 0; j < 4; ++j)
                            acc[i][j] += ha[i][kk] * wa[kk][j];
            }
            __syncthreads();
        }

        // write split-K partials
        #pragma unroll
        for (int i = 0; i < 4; ++i) {
            int b = ty * 4 + i;
            float4 v = make_float4(acc[i][0], acc[i][1], acc[i][2], acc[i][3]);
            *(float4*)&g_partial[((kc * 64 + b) << 10) + jt * 64 + tx * 4] = v;
        }

        gbar();

        // Phase 2: reduce 8 partials + xproj, tanh, write h_t. 2 outputs/thread.
        #pragma unroll
        for (int r = 0; r < 2; ++r) {
            int o = bx * 512 + r * 256 + tid;   // 0..65535, j-contiguous
            int b = o >> 10, j = o & 1023;
            float s = g_xproj[((size_t)b * TT + t) * HH + j];
            #pragma unroll
            for (int c = 0; c < 8; ++c)
                s += __ldcg(&g_partial[((c * 64 + b) << 10) + j]);
            g_hs[((size_t)b * TT + t) * HH + j] = tanhf(s);
        }

        gbar();
    }
}

// ---------------------------------------------------------------------------
// Kernel 3: logits[r][v] = sum_k hs[r][k] * Wl[v][k] + bl[v]
// 64 rows x 96 cols (all V) per CTA, K in chunks of 32, 4x6 thread tile.
// ---------------------------------------------------------------------------
__global__ void __launch_bounds__(256) logits_kernel(const float* __restrict__ Wl,
                                                     const float* __restrict__ bl,
                                                     float* __restrict__ out)
{
    __shared__ float sa [64][36];    // hs tile [row][k]
    __shared__ float swl[32][100];   // Wl^T tile [k][v], stride 100 -> conflict-free reads

    const int tid = threadIdx.x;
    const int tx  = tid & 15;
    const int ty  = tid >> 4;
    const size_t row0 = (size_t)blockIdx.x * 64;
    const int v0  = tx * 6;

    float acc[4][6] = {};

    #pragma unroll 1
    for (int K0 = 0; K0 < HH; K0 += 32) {
        #pragma unroll
        for (int i = 0; i < 2; ++i) {
            int idx = tid + i * 256;
            int r = idx >> 3, k4 = (idx & 7) * 4;
            float4 v = *(const float4*)(g_hs + (row0 + r) * HH + K0 + k4);
            *(float4*)&sa[r][k4] = v;
        }
        #pragma unroll
        for (int i = 0; i < 3; ++i) {  // 768 float4 covering Wl[0:96][K0:K0+32], transposed store
            int idx = tid + i * 256;
            int vv = idx >> 3, k4 = (idx & 7) * 4;
            float4 v = *(const float4*)(Wl + (size_t)vv * HH + K0 + k4);
            swl[k4 + 0][vv] = v.x;
            swl[k4 + 1][vv] = v.y;
            swl[k4 + 2][vv] = v.z;
            swl[k4 + 3][vv] = v.w;
        }
        __syncthreads();
        #pragma unroll 4
        for (int k = 0; k < 32; ++k) {
            float a0 = sa[ty * 4 + 0][k];
            float a1 = sa[ty * 4 + 1][k];
            float a2 = sa[ty * 4 + 2][k];
            float a3 = sa[ty * 4 + 3][k];
            #pragma unroll
            for (int j = 0; j < 6; ++j) {
                float w = swl[k][v0 + j];
                acc[0][j] += a0 * w;
                acc[1][j] += a1 * w;
                acc[2][j] += a2 * w;
                acc[3][j] += a3 * w;
            }
        }
        __syncthreads();
    }

    #pragma unroll
    for (int i = 0; i < 4; ++i)
        #pragma unroll
        for (int j = 0; j < 6; ++j)
            out[(row0 + ty * 4 + i) * VV + v0 + j] = acc[i][j] + bl[v0 + j];
}

// ---------------------------------------------------------------------------
// Kernel 4: h_last = hs[:, T-1, :]
// ---------------------------------------------------------------------------
__global__ void __launch_bounds__(256) hlast_kernel(float* __restrict__ out)
{
    int i = blockIdx.x * 256 + threadIdx.x;   // 0..65535
    int b = i >> 10, j = i & 1023;
    out[i] = g_hs[((size_t)b * TT + (TT - 1)) * HH + j];
}

// ---------------------------------------------------------------------------
extern "C" void kernel_launch(void* const* d_in, const int* in_sizes, int n_in,
                              void* d_out, int out_size)
{
    const float* x   = (const float*)d_in[0];
    const float* h0  = (const float*)d_in[1];
    const float* Wxh = (const float*)d_in[2];
    const float* Whh = (const float*)d_in[3];
    const float* bh  = (const float*)d_in[4];
    const float* Wl  = (const float*)d_in[5];
    const float* bl  = (const float*)d_in[6];
    float* out = (float*)d_out;
    (void)in_sizes; (void)n_in;

    xproj_kernel <<<dim3(16, (BB * TT) / 64), 256>>>(x, Wxh, bh);
    rnn_kernel   <<<NCTA, 256>>>(h0, Whh);
    logits_kernel<<<(BB * TT) / 64, 256>>>(Wl, bl, out);

    const size_t logits_elems = (size_t)BB * TT * VV;
    if ((size_t)out_size >= logits_elems + (size_t)BB * HH)
        hlast_kernel<<<(BB * HH) / 256, 256>>>(out + logits_elems);
}